// round 17
// baseline (speedup 1.0000x reference)
#include <cuda_runtime.h>
#include <cuda_bf16.h>
#include <cstdint>
#include <cstddef>

#define NN 100000
#define NE 600000
#define D  128
#define NR 16
#define NB 8
#define TM 128                 // tile rows (sources per tile)
#define NSEG (NR + 1)          // 16 relations + self
#define NCTA 148
#define NTH  512               // 16 warps, 4x4 warp grid (M32 x N32 each)

// ---------------- scratch (device globals only) ----------------
__device__ __nv_bfloat16 g_Wh[NSEG * D * D];
__device__ __nv_bfloat16 g_Wl[NSEG * D * D];
__device__ int g_bucket[NE];
__device__ int g_cnt[NR];
__device__ int g_off[NR];
__device__ int g_pos[NR];
__device__ int g_tgoff[NSEG + 1];
__device__ int g_is64;

// ---------------- helpers ----------------
__device__ __forceinline__ uint32_t smem_u32(const void* p) {
    uint32_t a;
    asm("{ .reg .u64 t; cvta.to.shared.u64 t, %1; cvt.u32.u64 %0, t; }"
        : "=r"(a) : "l"(p));
    return a;
}
// swizzled byte offset for element (row, col) in a 128x128 bf16 tile.
__device__ __forceinline__ uint32_t sw_off(int row, int col) {
    return (uint32_t)(row * 256 + ((((col >> 3) ^ (row & 7)) & 15) << 4)
                      + ((col & 7) << 1));
}

__device__ __forceinline__ void ldsm_x4(uint32_t* a, uint32_t addr) {
    asm volatile("ldmatrix.sync.aligned.m8n8.x4.shared.b16 {%0,%1,%2,%3}, [%4];"
                 : "=r"(a[0]), "=r"(a[1]), "=r"(a[2]), "=r"(a[3]) : "r"(addr));
}
__device__ __forceinline__ void mma16816(float* c, const uint32_t* a,
                                         uint32_t b0, uint32_t b1) {
    asm volatile(
        "mma.sync.aligned.m16n8k16.row.col.f32.bf16.bf16.f32 "
        "{%0,%1,%2,%3}, {%4,%5,%6,%7}, {%8,%9}, {%0,%1,%2,%3};"
        : "+f"(c[0]), "+f"(c[1]), "+f"(c[2]), "+f"(c[3])
        : "r"(a[0]), "r"(a[1]), "r"(a[2]), "r"(a[3]), "r"(b0), "r"(b1));
}

// ---------------- prep kernels (5 launches) ----------------
__global__ void k_detect(const void* etype_raw) {
    if (threadIdx.x < NR) g_cnt[threadIdx.x] = 0;
    if (threadIdx.x == 0 && blockIdx.x == 0) {
        const int* p = (const int*)etype_raw;
        int is64 = 1;
        for (int i = 1; i < 2000; i += 2)
            if (p[i] != 0) { is64 = 0; break; }
        g_is64 = is64;
    }
}

__global__ void k_weights(const float* __restrict__ bases,
                          const float* __restrict__ coeff,
                          const float* __restrict__ wself) {
    int idx = blockIdx.x * blockDim.x + threadIdx.x;
    if (idx >= NSEG * D * D) return;
    int r = idx / (D * D), rem = idx % (D * D);
    int o = rem >> 7, k = rem & 127;        // B[o][k] = W[k][o]
    float w;
    if (r < NR) {
        w = 0.f;
#pragma unroll
        for (int b = 0; b < NB; b++)
            w += coeff[r * NB + b] * bases[b * D * D + k * D + o];
    } else {
        w = wself[o * D + k];
    }
    __nv_bfloat16 wh = __float2bfloat16(w);
    __nv_bfloat16 wl = __float2bfloat16(w - __bfloat162float(wh));
    uint32_t off = sw_off(o, k);
    *(__nv_bfloat16*)((char*)g_Wh + (size_t)r * 32768 + off) = wh;
    *(__nv_bfloat16*)((char*)g_Wl + (size_t)r * 32768 + off) = wl;
}

__global__ void k_hist(const void* __restrict__ etype) {
    __shared__ int h[NR];
    if (threadIdx.x < NR) h[threadIdx.x] = 0;
    __syncthreads();
    const int is64 = g_is64;
    for (int e = blockIdx.x * blockDim.x + threadIdx.x; e < NE;
         e += gridDim.x * blockDim.x) {
        unsigned rel = is64 ? (unsigned)((const long long*)etype)[e]
                            : (unsigned)((const int*)etype)[e];
        if (rel < NR) atomicAdd(&h[rel], 1);
    }
    __syncthreads();
    if (threadIdx.x < NR) atomicAdd(&g_cnt[threadIdx.x], h[threadIdx.x]);
}

__global__ void k_scan() {
    if (threadIdx.x == 0) {
        int acc = 0, t = 0;
        for (int r = 0; r < NR; r++) {
            g_off[r] = acc; g_pos[r] = acc;
            g_tgoff[r] = t;
            acc += g_cnt[r];
            t += (g_cnt[r] + TM - 1) / TM;
        }
        g_tgoff[NR] = t;
        t += (NN + TM - 1) / TM;
        g_tgoff[NSEG] = t;
    }
}

__global__ void k_scatter(const void* __restrict__ etype, float4* __restrict__ out) {
    const int nz = NN * D / 4;       // fused: zero output
    for (int i = blockIdx.x * blockDim.x + threadIdx.x; i < nz;
         i += gridDim.x * blockDim.x)
        out[i] = make_float4(0.f, 0.f, 0.f, 0.f);

    __shared__ int h[NR];
    __shared__ int base[NR];
    if (threadIdx.x < NR) { h[threadIdx.x] = 0; base[threadIdx.x] = 0; }
    __syncthreads();
    const int is64 = g_is64;
    int e = blockIdx.x * blockDim.x + threadIdx.x;
    int rel = 0, rank = 0;
    bool ok = false;
    if (e < NE) {
        unsigned rr = is64 ? (unsigned)((const long long*)etype)[e]
                           : (unsigned)((const int*)etype)[e];
        if (rr < NR) { rel = (int)rr; ok = true; rank = atomicAdd(&h[rel], 1); }
    }
    __syncthreads();
    if (threadIdx.x < NR && h[threadIdx.x] > 0)
        base[threadIdx.x] = atomicAdd(&g_pos[threadIdx.x], h[threadIdx.x]);
    __syncthreads();
    if (ok) g_bucket[base[rel] + rank] = e;
}

// ---------------- main tensor-core apply ----------------
// dynamic SMEM (1KB aligned): Ah 32KB | Al 32KB | Bh 32KB | Bl 32KB
#define SM_AH 0
#define SM_AL 32768
#define SM_BH 65536
#define SM_BL 98304
#define SMEM_BYTES (131072 + 1024)

__global__ void __launch_bounds__(NTH, 1)
k_apply(const float* __restrict__ x,
        const void* __restrict__ eidx,
        float* __restrict__ out) {
    extern __shared__ char dynsm[];
    uint32_t rawb = smem_u32(dynsm);
    uint32_t dynbase = (rawb + 1023) & ~1023u;
    char* dynp = dynsm + (dynbase - rawb);

    __shared__ int s_rows[TM];
    __shared__ int s_cols[TM];
    __shared__ int s_cnt[NR], s_off[NR], s_tg[NSEG + 1];

    const int tid = threadIdx.x, wid = tid >> 5, lane = tid & 31;
    const int is64 = g_is64;
    if (tid < NR) { s_cnt[tid] = g_cnt[tid]; s_off[tid] = g_off[tid]; }
    if (tid <= NSEG) s_tg[tid] = g_tgoff[tid];
    __syncthreads();

    const int ntiles = s_tg[NSEG];
    const int chunk  = (ntiles + gridDim.x - 1) / gridDim.x;
    int t0 = blockIdx.x * chunk;
    int t1 = min(t0 + chunk, ntiles);

    int cur_r = -1;
    const uint32_t Ah_b = dynbase + SM_AH, Al_b = dynbase + SM_AL;
    const uint32_t Bh_b = dynbase + SM_BH, Bl_b = dynbase + SM_BL;

    // warp grid: mw = M group (rows mw*32..+32), nw = N group (cols nw*32..+32)
    const int mw = wid & 3, nw = wid >> 2;
    // A ldsm_x4 addressing (m16 x k16)
    const int a_lrow = lane & 15, a_half = lane >> 4;
    // B ldsm_x4 addressing (n16 x k16): 4 mats = (n0,k0),(n0,k1),(n1,k0),(n1,k1)
    const int b_lrow = (lane & 7) | ((lane >> 4) << 3);
    const int b_half = (lane >> 3) & 1;

    for (int t = t0; t < t1; t++) {
        int r = (cur_r < 0) ? 0 : cur_r;
        while (s_tg[r + 1] <= t) r++;

        __syncthreads();   // prior tile's smem reads done

        if (r != cur_r) {
            // front-batch all 8 LDG.128 (MLP=8) before the STS chain
            const float4* sh = (const float4*)((const char*)g_Wh + (size_t)r * 32768);
            const float4* sl = (const float4*)((const char*)g_Wl + (size_t)r * 32768);
            float4 vh[4], vl[4];
#pragma unroll
            for (int i = 0; i < 4; i++) vh[i] = __ldg(sh + tid + i * NTH);
#pragma unroll
            for (int i = 0; i < 4; i++) vl[i] = __ldg(sl + tid + i * NTH);
            float4* dh = (float4*)(dynp + SM_BH);
            float4* dl = (float4*)(dynp + SM_BL);
#pragma unroll
            for (int i = 0; i < 4; i++) {
                dh[tid + i * NTH] = vh[i];
                dl[tid + i * NTH] = vl[i];
            }
            cur_r = r;
        }

        const bool self  = (r == NR);
        const int  cnt   = self ? NN : s_cnt[r];
        const int  ebase = self ? 0  : s_off[r];
        const int  lt    = t - s_tg[r];

        // metadata: one source per thread (tids 0..127)
        if (tid < TM) {
            int ei = lt * TM + tid;
            int row = -1, col = -1;
            if (ei < cnt) {
                if (self) { row = ei; col = ei; }
                else {
                    int e = g_bucket[ebase + ei];
                    long long rw = is64 ? ((const long long*)eidx)[e]
                                        : (long long)((const int*)eidx)[e];
                    long long cl = is64 ? ((const long long*)eidx)[NE + e]
                                        : (long long)((const int*)eidx)[NE + e];
                    row = (int)(rw < 0 ? 0 : (rw >= NN ? NN - 1 : rw));
                    col = (int)(cl < 0 ? 0 : (cl >= NN ? NN - 1 : cl));
                }
            }
            s_rows[tid] = row;
            s_cols[tid] = col;
        }
        __syncthreads();

        // gather + hi/lo bf16 split into swizzled A tiles (512 threads)
        {
            char* Ah = dynp + SM_AH;
            char* Al = dynp + SM_AL;
            int rr = tid >> 2;
            int cc = s_cols[rr];
            const float4* xrow = (const float4*)(x + (size_t)(cc < 0 ? 0 : cc) * D);
#pragma unroll
            for (int j = 0; j < 4; j++) {
                int q = (tid & 3) + j * 4;          // 16B chunk (8 elems)
                float4 v0, v1;
                if (cc >= 0) {
                    v0 = __ldg(xrow + q * 2);
                    v1 = __ldg(xrow + q * 2 + 1);
                } else {
                    v0 = make_float4(0.f, 0.f, 0.f, 0.f);
                    v1 = v0;
                }
                uint32_t h[4], l[4];
                float4 vv[2] = {v0, v1};
#pragma unroll
                for (int m = 0; m < 2; m++) {
                    uint32_t h01, h23;
                    asm("cvt.rn.bf16x2.f32 %0, %1, %2;" : "=r"(h01)
                        : "f"(vv[m].y), "f"(vv[m].x));
                    asm("cvt.rn.bf16x2.f32 %0, %1, %2;" : "=r"(h23)
                        : "f"(vv[m].w), "f"(vv[m].z));
                    float hx = __uint_as_float(h01 << 16);
                    float hy = __uint_as_float(h01 & 0xffff0000u);
                    float hz = __uint_as_float(h23 << 16);
                    float hw = __uint_as_float(h23 & 0xffff0000u);
                    uint32_t l01, l23;
                    asm("cvt.rn.bf16x2.f32 %0, %1, %2;" : "=r"(l01)
                        : "f"(vv[m].y - hy), "f"(vv[m].x - hx));
                    asm("cvt.rn.bf16x2.f32 %0, %1, %2;" : "=r"(l23)
                        : "f"(vv[m].w - hw), "f"(vv[m].z - hz));
                    h[m * 2] = h01; h[m * 2 + 1] = h23;
                    l[m * 2] = l01; l[m * 2 + 1] = l23;
                }
                uint32_t off = sw_off(rr, q * 8);
                *(uint4*)(Ah + off) = make_uint4(h[0], h[1], h[2], h[3]);
                *(uint4*)(Al + off) = make_uint4(l[0], l[1], l[2], l[3]);
            }
        }
        __syncthreads();

        // ---- mma mainloop: warp = M32 x N32 tile ----
        float acc[8][4];   // [mg*4 + ng*2 + nh]
#pragma unroll
        for (int n = 0; n < 8; n++)
#pragma unroll
            for (int q = 0; q < 4; q++) acc[n][q] = 0.f;

#pragma unroll
        for (int kb = 0; kb < 8; kb++) {
            uint32_t ah[2][4], al[2][4], bh[2][4], bl[2][4];
#pragma unroll
            for (int mg = 0; mg < 2; mg++) {
                uint32_t aoff = sw_off(mw * 32 + mg * 16 + a_lrow,
                                       (kb * 2 + a_half) * 8);
                ldsm_x4(ah[mg], Ah_b + aoff);
                ldsm_x4(al[mg], Al_b + aoff);
            }
#pragma unroll
            for (int ng = 0; ng < 2; ng++) {
                uint32_t boff = sw_off(nw * 32 + ng * 16 + b_lrow,
                                       (kb * 2 + b_half) * 8);
                ldsm_x4(bh[ng], Bh_b + boff);
                ldsm_x4(bl[ng], Bl_b + boff);
            }
#pragma unroll
            for (int mg = 0; mg < 2; mg++)
#pragma unroll
                for (int ng = 0; ng < 2; ng++)
#pragma unroll
                    for (int nh = 0; nh < 2; nh++) {
                        float* c = acc[mg * 4 + ng * 2 + nh];
                        uint32_t b0h = bh[ng][nh * 2], b1h = bh[ng][nh * 2 + 1];
                        uint32_t b0l = bl[ng][nh * 2], b1l = bl[ng][nh * 2 + 1];
                        mma16816(c, ah[mg], b0h, b1h);
                        mma16816(c, al[mg], b0h, b1h);
                        mma16816(c, ah[mg], b0l, b1l);
                    }
        }

        // ---- epilogue: frag (row = l/4 [+8], col = nb*8 + (l%4)*2) ----
        {
            int cb = (lane & 3) * 2;
#pragma unroll
            for (int mg = 0; mg < 2; mg++) {
                int r0 = s_rows[mw * 32 + mg * 16 + (lane >> 2)];
                int r1 = s_rows[mw * 32 + mg * 16 + (lane >> 2) + 8];
#pragma unroll
                for (int nb = 0; nb < 4; nb++) {
                    int col = nw * 32 + nb * 8 + cb;
                    float* c = acc[mg * 4 + nb];
                    if (r0 >= 0)
                        asm volatile("red.global.add.v2.f32 [%0], {%1, %2};"
                                     :: "l"(out + (size_t)r0 * D + col),
                                        "f"(c[0]), "f"(c[1]) : "memory");
                    if (r1 >= 0)
                        asm volatile("red.global.add.v2.f32 [%0], {%1, %2};"
                                     :: "l"(out + (size_t)r1 * D + col),
                                        "f"(c[2]), "f"(c[3]) : "memory");
                }
            }
        }
    }
}

// ---------------- launcher ----------------
extern "C" void kernel_launch(void* const* d_in, const int* in_sizes, int n_in,
                              void* d_out, int out_size) {
    const float* x     = nullptr;
    const void*  eidx  = nullptr;
    const void*  etype = nullptr;
    const float* bases = nullptr;
    const float* coeff = nullptr;
    const float* wself = nullptr;
    for (int i = 0; i < n_in; i++) {
        switch (in_sizes[i]) {
            case NN * D:      x     = (const float*)d_in[i]; break;
            case 2 * NE:      eidx  = d_in[i];               break;
            case NE:          etype = d_in[i];               break;
            case NB * D * D:  bases = (const float*)d_in[i]; break;
            case NR * NB:     coeff = (const float*)d_in[i]; break;
            case D * D:       wself = (const float*)d_in[i]; break;
            default: break;
        }
    }
    float* out = (float*)d_out;

    cudaFuncSetAttribute((const void*)k_apply,
                         cudaFuncAttributeMaxDynamicSharedMemorySize, SMEM_BYTES);

    k_detect<<<1, 32>>>(etype);
    k_weights<<<(NSEG * D * D + 255) / 256, 256>>>(bases, coeff, wself);
    k_hist<<<512, 256>>>(etype);
    k_scan<<<1, 32>>>();
    k_scatter<<<(NE + 255) / 256, 256>>>(etype, (float4*)out);

    k_apply<<<NCTA, NTH, SMEM_BYTES>>>(x, eidx, out);
}